// round 7
// baseline (speedup 1.0000x reference)
#include <cuda_runtime.h>

#define BB 4
#define CC 64
#define NN 8192
#define OO 128
#define KK 20

typedef unsigned int u32;

// Scratch (static device allocations — no cudaMalloc anywhere)
__device__ __align__(16) float g_xt[(size_t)BB * NN * CC];   // x^T fp32 (mlp)
__device__ __align__(16) float g_xhi[(size_t)BB * NN * CC];  // tf32 hi part
__device__ __align__(16) float g_xlo[(size_t)BB * NN * CC];  // tf32 lo part
__device__ __align__(16) float g_xx[BB * NN];                // 0.5*||x||^2 fp32
__device__ int   g_knn[(size_t)BB * NN * KK];   // top-K indices
__device__ float g_W1at[CC * CC];               // [j][c] = W1[c][j],    c<64
__device__ float g_W1bt[CC * CC];               // [j][c] = W1[c][64+j], c<64
__device__ float g_W2t[2 * CC * OO];            // [c][o] = W2[o][c]

// ---- tf32 helpers ---------------------------------------------------------
__device__ __forceinline__ float tf32_round(float v) {
    u32 u; asm("cvt.rna.tf32.f32 %0, %1;" : "=r"(u) : "f"(v));
    return __uint_as_float(u);
}
__device__ __forceinline__ void mma_tf32(float& c0, float& c1, float& c2, float& c3,
                                         u32 a0, u32 a1, u32 a2, u32 a3,
                                         u32 b0, u32 b1) {
    asm("mma.sync.aligned.m16n8k8.row.col.f32.tf32.tf32.f32 "
        "{%0,%1,%2,%3},{%4,%5,%6,%7},{%8,%9},{%0,%1,%2,%3};"
        : "+f"(c0), "+f"(c1), "+f"(c2), "+f"(c3)
        : "r"(a0), "r"(a1), "r"(a2), "r"(a3), "r"(b0), "r"(b1));
}

// ---------------------------------------------------------------------------
// Prep: tiled transpose x -> xt (fp32) + tf32 hi/lo split + 0.5*norms
// ---------------------------------------------------------------------------
__global__ __launch_bounds__(256) void prep_x_kernel(const float* __restrict__ x) {
    int b = blockIdx.y;
    int n0 = blockIdx.x * 32;
    __shared__ float sh[CC][33];
    const float* xb = x + (size_t)b * CC * NN;
    int tid = threadIdx.x;
#pragma unroll
    for (int it = 0; it < 8; it++) {
        int e = it * 256 + tid;
        int c = e >> 5, nl = e & 31;
        sh[c][nl] = __ldg(&xb[(size_t)c * NN + n0 + nl]);  // coalesced
    }
    __syncthreads();
#pragma unroll
    for (int it = 0; it < 8; it++) {
        int e = it * 256 + tid;
        int nl = e >> 6, c = e & 63;
        float v = sh[c][nl];
        size_t o = ((size_t)b * NN + n0 + nl) * CC + c;
        g_xt[o] = v;
        float hi = tf32_round(v);
        g_xhi[o] = hi;
        g_xlo[o] = tf32_round(v - hi);
    }
    if (tid < 32) {
        float s = 0.f;
#pragma unroll
        for (int c = 0; c < CC; c++) { float v = sh[c][tid]; s += v * v; }
        g_xx[b * NN + n0 + tid] = 0.5f * s;
    }
}

// ---------------------------------------------------------------------------
// Prep weights. Only W1 rows c<64 needed (softmax over k sums to 1, so gate
// columns c>=64 contribute exactly center).
// ---------------------------------------------------------------------------
__global__ void prep_w_kernel(const float* __restrict__ W1,
                              const float* __restrict__ W2) {
    int t = blockIdx.x * 256 + threadIdx.x;  // 0..32767
    if (t < 128 * 128) {
        int c = t >> 7, j = t & 127;
        float v = W1[t];
        if (c < CC) {
            if (j < CC) g_W1at[j * CC + c] = v;
            else        g_W1bt[(j - CC) * CC + c] = v;
        }
    } else {
        int t2 = t - 128 * 128;
        int o = t2 >> 7, c2 = t2 & 127;
        g_W2t[c2 * OO + o] = W2[t2];
    }
}

// ---------------------------------------------------------------------------
// Top-K insertion (sorted desc, static indices). Strict '>' keeps earliest
// index on ties, matching jax.lax.top_k.
// ---------------------------------------------------------------------------
__device__ __forceinline__ void topk_insert(float (&vals)[KK], int (&idxs)[KK],
                                            float v, int j) {
    vals[KK - 1] = v;
    idxs[KK - 1] = j;
#pragma unroll
    for (int p = KK - 1; p > 0; --p) {
        if (vals[p] > vals[p - 1]) {
            float tv = vals[p]; vals[p] = vals[p - 1]; vals[p - 1] = tv;
            int   ti = idxs[p]; idxs[p] = idxs[p - 1]; idxs[p - 1] = ti;
        }
    }
}

// ---------------------------------------------------------------------------
// KNN via tensor cores. Block = 128 threads (4 warps) owns 64 queries.
// Query A-fragments (split-tf32 hi/lo, K=64) are register-resident per warp
// (warp w handles query rows w*16..w*16+15). Candidates processed in tiles
// of 64 (two 32-halves through one smem buffer). Scores = dot(xi,xj) via
// 3-pass split-tf32 mma (hihi + hilo + lohi), written to smem; 64 threads
// then scan rows with a 32-wide fmax guard and register top-20 insert.
// rank = dot - 0.5*||xj||^2 (monotone in pd; query term constant).
// ---------------------------------------------------------------------------
#define CPITCH 68  // floats; 4n+k bank-unique for B-frag loads, 16B-aligned rows
__global__ __launch_bounds__(128) void knn_mma_kernel() {
    __shared__ __align__(16) float sB[2][32][CPITCH];   // [hi/lo][cand][k]
    __shared__ __align__(16) float sScores[64][CPITCH]; // also query staging
    __shared__ __align__(16) float sXX[64];

    int b = blockIdx.y;
    int strip = blockIdx.x * 64;
    int tid = threadIdx.x;
    int w = tid >> 5, lane = tid & 31;
    int grp = lane >> 2, qd = lane & 3;
    const float* xhib = g_xhi + (size_t)b * NN * CC;
    const float* xlob = g_xlo + (size_t)b * NN * CC;

    // ---- stage queries & build A fragments (hi then lo) ----
    u32 ahi[8][4], alo[8][4];
#pragma unroll
    for (int pass = 0; pass < 2; pass++) {
        const float* src = pass ? xlob : xhib;
#pragma unroll
        for (int r = 0; r < 8; r++) {
            int idx = r * 128 + tid;
            int row = idx >> 4, f4 = idx & 15;
            *(float4*)&sScores[row][f4 * 4] =
                __ldg((const float4*)&src[(size_t)(strip + row) * CC + f4 * 4]);
        }
        __syncthreads();
        int qrow = w * 16 + grp;
#pragma unroll
        for (int kc = 0; kc < 8; kc++) {
            u32 f0 = __float_as_uint(sScores[qrow][kc * 8 + qd]);
            u32 f1 = __float_as_uint(sScores[qrow + 8][kc * 8 + qd]);
            u32 f2 = __float_as_uint(sScores[qrow][kc * 8 + qd + 4]);
            u32 f3 = __float_as_uint(sScores[qrow + 8][kc * 8 + qd + 4]);
            if (pass) { alo[kc][0] = f0; alo[kc][1] = f1; alo[kc][2] = f2; alo[kc][3] = f3; }
            else      { ahi[kc][0] = f0; ahi[kc][1] = f1; ahi[kc][2] = f2; ahi[kc][3] = f3; }
        }
        __syncthreads();
    }

    float vals[KK]; int idxs[KK];
#pragma unroll
    for (int k = 0; k < KK; k++) { vals[k] = -3.0e38f; idxs[k] = 0; }

    for (int jt = 0; jt < NN / 64; jt++) {
        int J = jt * 64;
        if (tid < 64) sXX[tid] = g_xx[b * NN + J + tid];

#pragma unroll 1
        for (int h = 0; h < 2; h++) {
            // fill sB with 32 candidates (hi + lo): 4 float4 each x 2
#pragma unroll
            for (int r = 0; r < 4; r++) {
                int idx = r * 128 + tid;
                int cand = idx >> 4, f4 = idx & 15;
                *(float4*)&sB[0][cand][f4 * 4] =
                    __ldg((const float4*)&xhib[(size_t)(J + h * 32 + cand) * CC + f4 * 4]);
                *(float4*)&sB[1][cand][f4 * 4] =
                    __ldg((const float4*)&xlob[(size_t)(J + h * 32 + cand) * CC + f4 * 4]);
            }
            __syncthreads();

            // mma: 4 n-blocks of 8 candidates
#pragma unroll 1
            for (int nb = 0; nb < 4; nb++) {
                float c0 = 0.f, c1 = 0.f, c2 = 0.f, c3 = 0.f;
                int n = nb * 8 + grp;
#pragma unroll
                for (int kc = 0; kc < 8; kc++) {
                    u32 bh0 = __float_as_uint(sB[0][n][kc * 8 + qd]);
                    u32 bh1 = __float_as_uint(sB[0][n][kc * 8 + qd + 4]);
                    u32 bl0 = __float_as_uint(sB[1][n][kc * 8 + qd]);
                    u32 bl1 = __float_as_uint(sB[1][n][kc * 8 + qd + 4]);
                    mma_tf32(c0, c1, c2, c3, ahi[kc][0], ahi[kc][1], ahi[kc][2], ahi[kc][3], bh0, bh1);
                    mma_tf32(c0, c1, c2, c3, ahi[kc][0], ahi[kc][1], ahi[kc][2], ahi[kc][3], bl0, bl1);
                    mma_tf32(c0, c1, c2, c3, alo[kc][0], alo[kc][1], alo[kc][2], alo[kc][3], bh0, bh1);
                }
                int col = h * 32 + nb * 8 + qd * 2;
                *(float2*)&sScores[w * 16 + grp][col] = make_float2(c0, c1);
                *(float2*)&sScores[w * 16 + grp + 8][col] = make_float2(c2, c3);
            }
            __syncthreads();
        }

        // ---- scan: thread q (tid<64) selects from its 64 scores ----
        if (tid < 64) {
            const float4* row = (const float4*)sScores[tid];
            const float4* xx4 = (const float4*)sXX;
            float th = vals[KK - 1];
#pragma unroll
            for (int h2 = 0; h2 < 2; h2++) {
                float mx = -3.0e38f;
#pragma unroll
                for (int g = 0; g < 8; g++) {
                    float4 s = row[h2 * 8 + g];
                    float4 x4 = xx4[h2 * 8 + g];
                    mx = fmaxf(mx, fmaxf(fmaxf(s.x - x4.x, s.y - x4.y),
                                         fmaxf(s.z - x4.z, s.w - x4.w)));
                }
                if (mx > th) {
#pragma unroll
                    for (int g = 0; g < 8; g++) {
                        float4 s = row[h2 * 8 + g];
                        float4 x4 = xx4[h2 * 8 + g];
                        int jb = J + h2 * 32 + g * 4;
                        float r0 = s.x - x4.x, r1 = s.y - x4.y;
                        float r2 = s.z - x4.z, r3 = s.w - x4.w;
                        if (r0 > vals[KK - 1]) topk_insert(vals, idxs, r0, jb + 0);
                        if (r1 > vals[KK - 1]) topk_insert(vals, idxs, r1, jb + 1);
                        if (r2 > vals[KK - 1]) topk_insert(vals, idxs, r2, jb + 2);
                        if (r3 > vals[KK - 1]) topk_insert(vals, idxs, r3, jb + 3);
                    }
                }
            }
        }
        __syncthreads();
    }

    if (tid < 64) {
        int* op = g_knn + ((size_t)b * NN + strip + tid) * KK;
#pragma unroll
        for (int k = 0; k < KK; k++) op[k] = idxs[k];
    }
}

// ---------------------------------------------------------------------------
// Fused MLP (exact round-2 code, known 358us): 4 points/block; thread
// (p = tid>>6, c = tid&63) owns column c (<64) of point p.
// ---------------------------------------------------------------------------
__global__ __launch_bounds__(256) void mlp_kernel(float* __restrict__ out) {
    int b = blockIdx.y;
    int n0 = blockIdx.x * 4;
    int tid = threadIdx.x;
    int p = tid >> 6, c = tid & 63;

    __shared__ __align__(16) float nbrT[4][CC][24];  // diff[j][k], pitch 24
    __shared__ float xi_sh[4][CC];
    __shared__ int   idx_sh[4][KK];
    __shared__ float g_sh[4][2 * CC];

    const float* xtb = g_xt + (size_t)b * NN * CC;

    if (tid < 4 * KK) {
        int pp = tid / KK, k = tid % KK;
        idx_sh[pp][k] = g_knn[((size_t)b * NN + n0 + pp) * KK + k];
    }
    xi_sh[p][c] = __ldg(&xtb[(size_t)(n0 + p) * CC + c]);
    __syncthreads();

    // gather neighbors and form diff = xj - xi, stored transposed [c][k]
    for (int pp = 0; pp < 4; pp++) {
        for (int e = tid; e < KK * CC; e += 256) {
            int k = e >> 6, cc = e & 63;
            nbrT[pp][cc][k] =
                __ldg(&xtb[(size_t)idx_sh[pp][k] * CC + cc]) - xi_sh[pp][cc];
        }
    }
    __syncthreads();

    // h[k] for this thread's column c (<64) of point p
    float h[KK];
#pragma unroll
    for (int k = 0; k < KK; k++) h[k] = 0.f;
    float base = 0.f;
#pragma unroll 8
    for (int j = 0; j < CC; j++) {
        float w  = __ldg(&g_W1at[j * CC + c]);          // coalesced, L1-hot
        base    += __ldg(&g_W1bt[j * CC + c]) * xi_sh[p][j];
        const float4* f4 = (const float4*)nbrT[p][j];   // broadcast
#pragma unroll
        for (int q = 0; q < 5; q++) {
            float4 f = f4[q];
            h[4 * q + 0] += f.x * w;
            h[4 * q + 1] += f.y * w;
            h[4 * q + 2] += f.z * w;
            h[4 * q + 3] += f.w * w;
        }
    }

    // softmax over k, then g
    float m = -3.0e38f;
#pragma unroll
    for (int k = 0; k < KK; k++) { h[k] += base; m = fmaxf(m, h[k]); }
    float s = 0.f;
#pragma unroll
    for (int k = 0; k < KK; k++) { h[k] = __expf(h[k] - m); s += h[k]; }
    float inv = 1.f / s;
    float gdiff = 0.f;
#pragma unroll
    for (int k = 0; k < KK; k++) gdiff += nbrT[p][c][k] * h[k];
    g_sh[p][c]      = gdiff * inv;
    g_sh[p][CC + c] = xi_sh[p][c];  // softmax sums to 1 -> center passthrough
    __syncthreads();

    // out[o] = sum_c W2[o][c] * g[c]
    int o = tid & 127;
    int pb = (tid >> 7) * 2;
    for (int r = 0; r < 2; r++) {
        int pp = pb + r;
        float acc = 0.f;
#pragma unroll 16
        for (int cc = 0; cc < 2 * CC; cc++)
            acc += __ldg(&g_W2t[cc * OO + o]) * g_sh[pp][cc];
        out[(size_t)b * OO * NN + (size_t)o * NN + (n0 + pp)] = acc;
    }
}

// ---------------------------------------------------------------------------
extern "C" void kernel_launch(void* const* d_in, const int* in_sizes, int n_in,
                              void* d_out, int out_size) {
    const float* x  = (const float*)d_in[0];
    const float* W1 = (const float*)d_in[1];
    const float* W2 = (const float*)d_in[2];
    float* out = (float*)d_out;

    prep_x_kernel<<<dim3(NN / 32, BB), 256>>>(x);
    prep_w_kernel<<<128, 256>>>(W1, W2);
    knn_mma_kernel<<<dim3(NN / 64, BB), 128>>>();
    mlp_kernel<<<dim3(NN / 4, BB), 256>>>(out);
}

// round 8
// speedup vs baseline: 4.1478x; 4.1478x over previous
#include <cuda_runtime.h>

#define BB 4
#define CC 64
#define NN 8192
#define OO 128
#define KK 20

typedef unsigned long long u64;

// Scratch (static device allocations — no cudaMalloc anywhere)
__device__ __align__(16) float g_xt[(size_t)BB * NN * CC];  // x^T: [b][n][c]
__device__ float g_xx[BB * NN];                 // 0.5 * squared norms
__device__ int   g_knn[(size_t)BB * NN * KK];   // top-K indices
__device__ float g_W1at[CC * CC];               // [j][c] = W1[c][j],    c<64
__device__ float g_W1bt[CC * CC];               // [j][c] = W1[c][64+j], c<64
__device__ float g_W2t[2 * CC * OO];            // [c][o] = W2[o][c]

// ---- packed fp32x2 helpers (bit-exact fp32, 2 MACs/issue) -----------------
__device__ __forceinline__ u64 fma2(u64 a, u64 b, u64 c) {
    u64 d; asm("fma.rn.f32x2 %0, %1, %2, %3;" : "=l"(d) : "l"(a), "l"(b), "l"(c));
    return d;
}
__device__ __forceinline__ u64 add2(u64 a, u64 b) {
    u64 d; asm("add.rn.f32x2 %0, %1, %2;" : "=l"(d) : "l"(a), "l"(b));
    return d;
}
__device__ __forceinline__ u64 pack2(float lo, float hi) {
    u64 d; asm("mov.b64 %0, {%1, %2};" : "=l"(d) : "f"(lo), "f"(hi));
    return d;
}
__device__ __forceinline__ void unpack2(float& lo, float& hi, u64 v) {
    asm("mov.b64 {%0, %1}, %2;" : "=f"(lo), "=f"(hi) : "l"(v));
}

// ---------------------------------------------------------------------------
// Prep: tiled transpose x -> xt[b][n][c] (coalesced both sides) + 0.5*norms
// ---------------------------------------------------------------------------
__global__ __launch_bounds__(256) void prep_x_kernel(const float* __restrict__ x) {
    int b = blockIdx.y;
    int n0 = blockIdx.x * 32;
    __shared__ float sh[CC][33];
    const float* xb = x + (size_t)b * CC * NN;
    int tid = threadIdx.x;
#pragma unroll
    for (int it = 0; it < 8; it++) {
        int e = it * 256 + tid;
        int c = e >> 5, nl = e & 31;
        sh[c][nl] = __ldg(&xb[(size_t)c * NN + n0 + nl]);  // coalesced
    }
    __syncthreads();
#pragma unroll
    for (int it = 0; it < 8; it++) {
        int e = it * 256 + tid;
        int nl = e >> 6, c = e & 63;
        g_xt[((size_t)b * NN + n0 + nl) * CC + c] = sh[c][nl];  // coalesced
    }
    if (tid < 32) {
        float s = 0.f;
#pragma unroll
        for (int c = 0; c < CC; c++) { float v = sh[c][tid]; s += v * v; }
        g_xx[b * NN + n0 + tid] = 0.5f * s;
    }
}

// ---------------------------------------------------------------------------
// Prep weights. Only W1 rows c<64 needed (softmax over k sums to 1, so gate
// columns c>=64 contribute exactly center).
// ---------------------------------------------------------------------------
__global__ void prep_w_kernel(const float* __restrict__ W1,
                              const float* __restrict__ W2) {
    int t = blockIdx.x * 256 + threadIdx.x;  // 0..32767
    if (t < 128 * 128) {
        int c = t >> 7, j = t & 127;
        float v = W1[t];
        if (c < CC) {
            if (j < CC) g_W1at[j * CC + c] = v;
            else        g_W1bt[(j - CC) * CC + c] = v;
        }
    } else {
        int t2 = t - 128 * 128;
        int o = t2 >> 7, c2 = t2 & 127;
        g_W2t[c2 * OO + o] = W2[t2];
    }
}

// ---------------------------------------------------------------------------
// Top-K insertion (sorted desc, static indices). Strict '>' keeps earliest
// index on ties, matching jax.lax.top_k.
// ---------------------------------------------------------------------------
__device__ __forceinline__ void topk_insert(float (&vals)[KK], int (&idxs)[KK],
                                            float v, int j) {
    vals[KK - 1] = v;
    idxs[KK - 1] = j;
#pragma unroll
    for (int p = KK - 1; p > 0; --p) {
        if (vals[p] > vals[p - 1]) {
            float tv = vals[p]; vals[p] = vals[p - 1]; vals[p - 1] = tv;
            int   ti = idxs[p]; idxs[p] = idxs[p - 1]; idxs[p - 1] = ti;
        }
    }
}

// ---------------------------------------------------------------------------
// KNN: 1 query per thread, xi packed as 32 f32x2 regs, candidate chunk in
// shared. Inner loop computes EIGHT candidates' ranks in one branch-free
// region (one accumulator set, ranks buffered in regs), then one fmax-tree
// guard + insert block per 8 -> branch scaffolding amortized 8x and
// cross-candidate ILP (LDS latency hiding) enabled.
// rank = dot - 0.5*||xj||^2  (monotone in pd; xxi constant per query).
// ---------------------------------------------------------------------------
__global__ __launch_bounds__(128) void knn_kernel() {
    int b = blockIdx.y;
    int i = blockIdx.x * 128 + threadIdx.x;
    __shared__ __align__(16) float shx[128][CC];
    __shared__ float shxx[128];
    const float* xtb = g_xt + (size_t)b * NN * CC;

    u64 xi2[32];
    const float4* xir = (const float4*)(xtb + (size_t)i * CC);
#pragma unroll
    for (int q = 0; q < 16; q++) {
        float4 t = __ldg(&xir[q]);
        xi2[2 * q + 0] = pack2(t.x, t.y);
        xi2[2 * q + 1] = pack2(t.z, t.w);
    }

    float vals[KK]; int idxs[KK];
#pragma unroll
    for (int k = 0; k < KK; k++) { vals[k] = -3.0e38f; idxs[k] = 0; }

    for (int j0 = 0; j0 < NN; j0 += 128) {
        __syncthreads();
        const float4* src = (const float4*)(xtb + (size_t)j0 * CC);
        float4* dst = (float4*)shx;
#pragma unroll
        for (int r = 0; r < 16; r++) {
            int lin = r * 128 + threadIdx.x;
            dst[lin] = __ldg(&src[lin]);
        }
        shxx[threadIdx.x] = g_xx[b * NN + j0 + threadIdx.x];
        __syncthreads();

#pragma unroll 1
        for (int jl = 0; jl < 128; jl += 8) {
            float rank[8];
            // ---- branch-free: 8 sequential dots (ptxas pipelines across) --
#pragma unroll
            for (int u = 0; u < 8; u++) {
                const ulonglong2* row = (const ulonglong2*)shx[jl + u];
                u64 a0 = 0ull, a1 = 0ull, a2 = 0ull, a3 = 0ull;
#pragma unroll
                for (int q = 0; q < 8; q++) {
                    ulonglong2 v0 = row[2 * q];
                    ulonglong2 v1 = row[2 * q + 1];
                    a0 = fma2(xi2[4 * q + 0], v0.x, a0);
                    a1 = fma2(xi2[4 * q + 1], v0.y, a1);
                    a2 = fma2(xi2[4 * q + 2], v1.x, a2);
                    a3 = fma2(xi2[4 * q + 3], v1.y, a3);
                }
                a0 = add2(a0, a1);
                a2 = add2(a2, a3);
                a0 = add2(a0, a2);
                float lo, hi; unpack2(lo, hi, a0);
                rank[u] = lo + hi - shxx[jl + u];
            }
            // ---- one guard per 8 candidates ----
            float m01 = fmaxf(rank[0], rank[1]);
            float m23 = fmaxf(rank[2], rank[3]);
            float m45 = fmaxf(rank[4], rank[5]);
            float m67 = fmaxf(rank[6], rank[7]);
            float mx = fmaxf(fmaxf(m01, m23), fmaxf(m45, m67));
            if (mx > vals[KK - 1]) {
#pragma unroll
                for (int u = 0; u < 8; u++) {  // ascending j: jax tie-break
                    if (rank[u] > vals[KK - 1])
                        topk_insert(vals, idxs, rank[u], j0 + jl + u);
                }
            }
        }
    }
    int* op = g_knn + ((size_t)b * NN + i) * KK;
#pragma unroll
    for (int k = 0; k < KK; k++) op[k] = idxs[k];
}

// ---------------------------------------------------------------------------
// Fused MLP (exact round-2 code, known 358us): 4 points/block; thread
// (p = tid>>6, c = tid&63) owns column c (<64) of point p.
// ---------------------------------------------------------------------------
__global__ __launch_bounds__(256) void mlp_kernel(float* __restrict__ out) {
    int b = blockIdx.y;
    int n0 = blockIdx.x * 4;
    int tid = threadIdx.x;
    int p = tid >> 6, c = tid & 63;

    __shared__ __align__(16) float nbrT[4][CC][24];  // diff[j][k], pitch 24
    __shared__ float xi_sh[4][CC];
    __shared__ int   idx_sh[4][KK];
    __shared__ float g_sh[4][2 * CC];

    const float* xtb = g_xt + (size_t)b * NN * CC;

    if (tid < 4 * KK) {
        int pp = tid / KK, k = tid % KK;
        idx_sh[pp][k] = g_knn[((size_t)b * NN + n0 + pp) * KK + k];
    }
    xi_sh[p][c] = __ldg(&xtb[(size_t)(n0 + p) * CC + c]);
    __syncthreads();

    // gather neighbors and form diff = xj - xi, stored transposed [c][k]
    for (int pp = 0; pp < 4; pp++) {
        for (int e = tid; e < KK * CC; e += 256) {
            int k = e >> 6, cc = e & 63;
            nbrT[pp][cc][k] =
                __ldg(&xtb[(size_t)idx_sh[pp][k] * CC + cc]) - xi_sh[pp][cc];
        }
    }
    __syncthreads();

    // h[k] for this thread's column c (<64) of point p
    float h[KK];
#pragma unroll
    for (int k = 0; k < KK; k++) h[k] = 0.f;
    float base = 0.f;
#pragma unroll 8
    for (int j = 0; j < CC; j++) {
        float w  = __ldg(&g_W1at[j * CC + c]);          // coalesced, L1-hot
        base    += __ldg(&g_W1bt[j * CC + c]) * xi_sh[p][j];
        const float4* f4 = (const float4*)nbrT[p][j];   // broadcast
#pragma unroll
        for (int q = 0; q < 5; q++) {
            float4 f = f4[q];
            h[4 * q + 0] += f.x * w;
            h[4 * q + 1] += f.y * w;
            h[4 * q + 2] += f.z * w;
            h[4 * q + 3] += f.w * w;
        }
    }

    // softmax over k, then g
    float m = -3.0e38f;
#pragma unroll
    for (int k = 0; k < KK; k++) { h[k] += base; m = fmaxf(m, h[k]); }
    float s = 0.f;
#pragma unroll
    for (int k = 0; k < KK; k++) { h[k] = __expf(h[k] - m); s += h[k]; }
    float inv = 1.f / s;
    float gdiff = 0.f;
#pragma unroll
    for (int k = 0; k < KK; k++) gdiff += nbrT[p][c][k] * h[k];
    g_sh[p][c]      = gdiff * inv;
    g_sh[p][CC + c] = xi_sh[p][c];  // softmax sums to 1 -> center passthrough
    __syncthreads();

    // out[o] = sum_c W2[o][c] * g[c]
    int o = tid & 127;
    int pb = (tid >> 7) * 2;
    for (int r = 0; r < 2; r++) {
        int pp = pb + r;
        float acc = 0.f;
#pragma unroll 16
        for (int cc = 0; cc < 2 * CC; cc++)
            acc += __ldg(&g_W2t[cc * OO + o]) * g_sh[pp][cc];
        out[(size_t)b * OO * NN + (size_t)o * NN + (n0 + pp)] = acc;
    }
}

// ---------------------------------------------------------------------------
extern "C" void kernel_launch(void* const* d_in, const int* in_sizes, int n_in,
                              void* d_out, int out_size) {
    const float* x  = (const float*)d_in[0];
    const float* W1 = (const float*)d_in[1];
    const float* W2 = (const float*)d_in[2];
    float* out = (float*)d_out;

    prep_x_kernel<<<dim3(NN / 32, BB), 256>>>(x);
    prep_w_kernel<<<128, 256>>>(W1, W2);
    knn_kernel<<<dim3(NN / 128, BB), 128>>>();
    mlp_kernel<<<dim3(NN / 4, BB), 256>>>(out);
}